// round 1
// baseline (speedup 1.0000x reference)
#include <cuda_runtime.h>
#include <math.h>

// Problem constants
// B=32, T=512, N=1024, FT=16, FS=32, NCH=512, DIN=1024, H=1024, NP=1024
// x rows = 32*1025 = 32800, x elems = 33,587,200
#define XROWS 32800
#define XTOT  33587200LL

// Scratch for intermediate x1 = gelu(embed)*scale, padded to 257*128 = 32896 rows.
// Rows >= 32800 stay zero-initialized (never written) -> deterministic loads.
__device__ float g_x1[32896ull * 1024ull];

__device__ __forceinline__ unsigned f2tf(float f) {
    unsigned u;
    asm("cvt.rna.tf32.f32 %0, %1;" : "=r"(u) : "f"(f));
    return u;
}

// gelu(x) * 32 = 16 * x * (1 + erf(x/sqrt(2)))
__device__ __forceinline__ float gelu32(float x) {
    return 16.0f * x * (1.0f + erff(x * 0.7071067811865476f));
}

// MODE 0: A = patchified spikes (gather), B = W_embed [1024,512], K=512.
//         epilogue: gelu(acc + b_embed)*32 -> g_x1 row (b*1025 + 1 + p)
// MODE 1: A = g_x1 [32896,1024], B = W_proj [1024,1024], K=1024.
//         epilogue: acc + b_proj + pos_table[p] -> d_out row m (guard m<32800)
template<int MODE>
__global__ __launch_bounds__(256)
void fused_gemm(const float* __restrict__ Asrc,
                const float* __restrict__ Bsrc,
                const float* __restrict__ bias,
                const float* __restrict__ pos,
                float* __restrict__ outp)
{
    constexpr int K = (MODE == 0) ? 512 : 1024;
    __shared__ unsigned As[128][36];   // pad 36: 4g+t pattern is conflict-free
    __shared__ unsigned Bs[128][36];

    const int tid  = threadIdx.x;
    const int bm   = blockIdx.y;
    const int bn   = blockIdx.x;
    const int warp = tid >> 5;
    const int lane = tid & 31;
    const int g = lane >> 2;          // groupID (row within fragment)
    const int t = lane & 3;           // thread-in-group
    const int wm = (warp & 3) << 5;   // warp m offset: 0/32/64/96
    const int wn = (warp >> 2) << 6;  // warp n offset: 0/64

    const int lrow = tid >> 3;        // 0..31  (load row)
    const int lcol = (tid & 7) << 2;  // 0,4,...,28 (float4 col)

    float acc[2][8][4];
    #pragma unroll
    for (int i = 0; i < 2; i++)
        #pragma unroll
        for (int j = 0; j < 8; j++)
            #pragma unroll
            for (int e = 0; e < 4; e++) acc[i][j][e] = 0.0f;

    for (int kt = 0; kt < K; kt += 32) {
        #pragma unroll
        for (int it = 0; it < 4; it++) {
            const int row = lrow + (it << 5);
            const int m = bm * 128 + row;
            const float* ap;
            if (MODE == 0) {
                // patch gather: m -> (b, p); within a 32-wide K-tile the 32
                // channels (ft fixed = kt/32, fs = 0..31) are contiguous.
                const int b = m >> 10, p = m & 1023;
                const int pt = p >> 5, ps = p & 31;
                ap = Asrc + ((size_t)b << 19)
                          + ((size_t)((pt << 4) + (kt >> 5)) << 10)
                          + (ps << 5) + lcol;
            } else {
                ap = g_x1 + ((size_t)m << 10) + kt + lcol;
            }
            const float4 av = *(const float4*)ap;
            *(uint4*)&As[row][lcol] =
                make_uint4(f2tf(av.x), f2tf(av.y), f2tf(av.z), f2tf(av.w));

            const float4 bv = *(const float4*)(Bsrc + (size_t)(bn * 128 + row) * K + kt + lcol);
            *(uint4*)&Bs[row][lcol] =
                make_uint4(f2tf(bv.x), f2tf(bv.y), f2tf(bv.z), f2tf(bv.w));
        }
        __syncthreads();

        #pragma unroll
        for (int ks = 0; ks < 4; ks++) {
            const int k0 = ks << 3;
            unsigned af[2][4];
            #pragma unroll
            for (int mi = 0; mi < 2; mi++) {
                const int r = wm + (mi << 4) + g;
                af[mi][0] = As[r    ][k0 + t];
                af[mi][1] = As[r + 8][k0 + t];
                af[mi][2] = As[r    ][k0 + t + 4];
                af[mi][3] = As[r + 8][k0 + t + 4];
            }
            #pragma unroll
            for (int ni = 0; ni < 8; ni++) {
                const int c = wn + (ni << 3) + g;
                const unsigned bf0 = Bs[c][k0 + t];
                const unsigned bf1 = Bs[c][k0 + t + 4];
                #pragma unroll
                for (int mi = 0; mi < 2; mi++) {
                    asm volatile(
                        "mma.sync.aligned.m16n8k8.row.col.f32.tf32.tf32.f32 "
                        "{%0,%1,%2,%3}, {%4,%5,%6,%7}, {%8,%9}, {%0,%1,%2,%3};"
                        : "+f"(acc[mi][ni][0]), "+f"(acc[mi][ni][1]),
                          "+f"(acc[mi][ni][2]), "+f"(acc[mi][ni][3])
                        : "r"(af[mi][0]), "r"(af[mi][1]),
                          "r"(af[mi][2]), "r"(af[mi][3]),
                          "r"(bf0), "r"(bf1));
                }
            }
        }
        __syncthreads();
    }

    // Epilogue directly from accumulator fragments.
    // c0:(g, 2t) c1:(g, 2t+1) c2:(g+8, 2t) c3:(g+8, 2t+1)
    #pragma unroll
    for (int mi = 0; mi < 2; mi++) {
        const int m0 = bm * 128 + wm + (mi << 4) + g;
        const int m1 = m0 + 8;
        #pragma unroll
        for (int ni = 0; ni < 8; ni++) {
            const int n = bn * 128 + wn + (ni << 3) + (t << 1);
            const float2 bb = *(const float2*)(bias + n);
            if (MODE == 0) {
                {
                    const int b = m0 >> 10, p = m0 & 1023;
                    float2 v = make_float2(gelu32(acc[mi][ni][0] + bb.x),
                                           gelu32(acc[mi][ni][1] + bb.y));
                    *(float2*)&g_x1[((size_t)(b * 1025 + 1 + p) << 10) + n] = v;
                }
                {
                    const int b = m1 >> 10, p = m1 & 1023;
                    float2 v = make_float2(gelu32(acc[mi][ni][2] + bb.x),
                                           gelu32(acc[mi][ni][3] + bb.y));
                    *(float2*)&g_x1[((size_t)(b * 1025 + 1 + p) << 10) + n] = v;
                }
            } else {
                if (m0 < XROWS) {
                    const int b = m0 / 1025, p = m0 - b * 1025;
                    const float2 pv = *(const float2*)(pos + ((size_t)p << 10) + n);
                    float2 v = make_float2(acc[mi][ni][0] + bb.x + pv.x,
                                           acc[mi][ni][1] + bb.y + pv.y);
                    *(float2*)&outp[((size_t)m0 << 10) + n] = v;
                }
                if (m1 < XROWS) {
                    const int b = m1 / 1025, p = m1 - b * 1025;
                    const float2 pv = *(const float2*)(pos + ((size_t)p << 10) + n);
                    float2 v = make_float2(acc[mi][ni][2] + bb.x + pv.x,
                                           acc[mi][ni][3] + bb.y + pv.y);
                    *(float2*)&outp[((size_t)m1 << 10) + n] = v;
                }
            }
        }
    }
}

// cls rows of x1: row b*1025 gets gelu(cls_tokens)*32 (no bias).
__global__ void cls_kernel(const float* __restrict__ cls) {
    const int i = blockIdx.x * blockDim.x + threadIdx.x;
    if (i < 32 * 1024) {
        const int b = i >> 10, d = i & 1023;
        g_x1[((size_t)(b * 1025) << 10) + d] = gelu32(cls[d]);
    }
}

// mask (all 1.0) and stamp (arange % 1025) appended after x in d_out.
__global__ void tail_kernel(float* __restrict__ outp) {
    const int i = blockIdx.x * blockDim.x + threadIdx.x;
    if (i < XROWS) {
        outp[XTOT + i] = 1.0f;
        outp[XTOT + XROWS + i] = (float)(i % 1025);
    }
}

extern "C" void kernel_launch(void* const* d_in, const int* in_sizes, int n_in,
                              void* d_out, int out_size) {
    const float* spikes  = (const float*)d_in[0];
    const float* W_embed = (const float*)d_in[1];
    const float* b_embed = (const float*)d_in[2];
    const float* cls     = (const float*)d_in[3];
    const float* W_proj  = (const float*)d_in[4];
    const float* b_proj  = (const float*)d_in[5];
    const float* pos     = (const float*)d_in[6];
    float* outp = (float*)d_out;

    // x1 cls rows (independent of GEMM1's patch rows)
    cls_kernel<<<128, 256>>>(cls);

    // GEMM1: patchify + embed + gelu*scale -> g_x1   (M=32768, K=512, N=1024)
    fused_gemm<0><<<dim3(8, 256), 256>>>(spikes, W_embed, b_embed, nullptr, nullptr);

    // GEMM2: proj + bias + pos_table -> d_out        (M=32800, K=1024, N=1024)
    fused_gemm<1><<<dim3(8, 257), 256>>>(nullptr, W_proj, b_proj, pos, outp);

    // mask + stamp, if the output buffer carries them
    if ((long long)out_size >= XTOT + 2LL * XROWS) {
        tail_kernel<<<(XROWS + 255) / 256, 256>>>(outp);
    }
}

// round 2
// speedup vs baseline: 1.6441x; 1.6441x over previous
#include <cuda_runtime.h>
#include <math.h>

// B=32, T=512, N=1024, FT=16, FS=32, NCH=512, DIN=1024, H=1024
// x rows = 32*1025 = 32800
#define XROWS 32800
#define XTOT  33587200LL

// Scratch (device globals; zero-initialized). Rows >= 32800 of g_x1 stay zero.
__device__ float g_x1[32896ull * 1024ull];      // gelu(embed)*scale, tf32-rounded bits
__device__ float g_spk[16777216];                // tf32-rounded spikes
__device__ float g_we[524288];                   // tf32-rounded W_embed
__device__ float g_wp[1048576];                  // tf32-rounded W_proj

__device__ __forceinline__ unsigned f2tf(float f) {
    unsigned u;
    asm("cvt.rna.tf32.f32 %0, %1;" : "=r"(u) : "f"(f));
    return u;
}
__device__ __forceinline__ float f2tff(float f) {
    return __uint_as_float(f2tf(f));
}
__device__ __forceinline__ float gelu32(float x) {
    return 16.0f * x * (1.0f + erff(x * 0.7071067811865476f));
}

__device__ __forceinline__ void cp16(unsigned* dst, const float* src) {
    unsigned a = (unsigned)__cvta_generic_to_shared(dst);
    asm volatile("cp.async.cg.shared.global [%0], [%1], 16;" :: "r"(a), "l"(src));
}

// ---------------- pre-convert: spikes, W_embed, W_proj -> tf32 bits; cls -> g_x1 ----
#define SPK4 4194304u
#define WE4  131072u
#define WP4  262144u
#define CLS4 8192u
__global__ __launch_bounds__(256)
void convert_kernel(const float4* __restrict__ spk, const float4* __restrict__ we,
                    const float4* __restrict__ wp,  const float4* __restrict__ cls) {
    unsigned i = blockIdx.x * 256u + threadIdx.x;
    if (i < SPK4) {
        float4 v = spk[i];
        ((float4*)g_spk)[i] = make_float4(f2tff(v.x), f2tff(v.y), f2tff(v.z), f2tff(v.w));
    } else if (i < SPK4 + WE4) {
        unsigned j = i - SPK4;
        float4 v = we[j];
        ((float4*)g_we)[j] = make_float4(f2tff(v.x), f2tff(v.y), f2tff(v.z), f2tff(v.w));
    } else if (i < SPK4 + WE4 + WP4) {
        unsigned j = i - SPK4 - WE4;
        float4 v = wp[j];
        ((float4*)g_wp)[j] = make_float4(f2tff(v.x), f2tff(v.y), f2tff(v.z), f2tff(v.w));
    } else {
        unsigned j = i - SPK4 - WE4 - WP4;   // < 8192 : 32 batches x 256 float4
        unsigned b = j >> 8, q = j & 255;
        float4 v = cls[q];
        float4 r = make_float4(f2tff(gelu32(v.x)), f2tff(gelu32(v.y)),
                               f2tff(gelu32(v.z)), f2tff(gelu32(v.w)));
        ((float4*)g_x1)[(size_t)b * 1025u * 256u + q] = r;
    }
}

// ---------------- pipelined tf32 GEMM --------------------------------------
// Block tile 128x128, 8 warps of 32(M)x64(N), K-chunk 32, 3-stage cp.async.
// smem stage layout (words): A[128][32] swizzled, then B[128][32] swizzled.
// word(row, k) = row*32 + (k ^ ((row&7)<<2))   [16B-chunk-granular XOR swizzle]
#define STG_WORDS 8192
#define SMEM_BYTES (3 * STG_WORDS * 4)

template<int MODE>
__device__ __forceinline__ void issue_chunk(unsigned* smem, int s, int c,
                                            int bm, int bn, int tid) {
    constexpr int K = MODE ? 1024 : 512;
    const float* Bsrc = MODE ? g_wp : g_we;
    unsigned* As = smem + s * STG_WORDS;
    unsigned* Bs = As + 4096;
    #pragma unroll
    for (int j = 0; j < 4; j++) {
        int ci = tid + j * 256;          // 1024 chunks of 16B per operand
        int row = ci >> 3, ch = ci & 7;
        int word = row * 32 + ((ch ^ (row & 7)) << 2);
        const float* srcA;
        if (MODE == 0) {
            int m = bm * 128 + row;
            int b = m >> 10, p = m & 1023, pt = p >> 5, ps = p & 31;
            srcA = g_spk + ((size_t)b << 19) + ((size_t)((pt << 4) + c) << 10)
                         + (ps << 5) + ch * 4;
        } else {
            srcA = g_x1 + ((size_t)(bm * 128 + row) << 10) + c * 32 + ch * 4;
        }
        cp16(As + word, srcA);
        cp16(Bs + word, Bsrc + (size_t)(bn * 128 + row) * K + c * 32 + ch * 4);
    }
}

__device__ __forceinline__ void compute_chunk(const unsigned* As, const unsigned* Bs,
                                              float acc[2][8][4],
                                              int wm, int wn, int g, int t) {
    #pragma unroll
    for (int ks = 0; ks < 4; ks++) {
        const int col1 = ((ks << 3) + t) ^ (g << 2);
        const int col2 = col1 ^ 4;
        unsigned af[2][4];
        #pragma unroll
        for (int mi = 0; mi < 2; mi++) {
            const int r = wm + (mi << 4) + g;
            af[mi][0] = As[r * 32 + col1];
            af[mi][1] = As[(r + 8) * 32 + col1];
            af[mi][2] = As[r * 32 + col2];
            af[mi][3] = As[(r + 8) * 32 + col2];
        }
        #pragma unroll
        for (int ni = 0; ni < 8; ni++) {
            const int cc = wn + (ni << 3) + g;
            const unsigned b0 = Bs[cc * 32 + col1];
            const unsigned b1 = Bs[cc * 32 + col2];
            #pragma unroll
            for (int mi = 0; mi < 2; mi++) {
                asm volatile(
                    "mma.sync.aligned.m16n8k8.row.col.f32.tf32.tf32.f32 "
                    "{%0,%1,%2,%3}, {%4,%5,%6,%7}, {%8,%9}, {%0,%1,%2,%3};"
                    : "+f"(acc[mi][ni][0]), "+f"(acc[mi][ni][1]),
                      "+f"(acc[mi][ni][2]), "+f"(acc[mi][ni][3])
                    : "r"(af[mi][0]), "r"(af[mi][1]),
                      "r"(af[mi][2]), "r"(af[mi][3]),
                      "r"(b0), "r"(b1));
            }
        }
    }
}

template<int MODE>
__global__ __launch_bounds__(256, 2)
void fused_gemm(const float* __restrict__ bias, const float* __restrict__ pos,
                float* __restrict__ outp, int do_tail)
{
    constexpr int NC = MODE ? 32 : 16;   // K/32
    extern __shared__ unsigned smem[];
    const int tid  = threadIdx.x;
    const int bm   = blockIdx.y;
    const int bn   = blockIdx.x;
    const int warp = tid >> 5;
    const int lane = tid & 31;
    const int g = lane >> 2;
    const int t = lane & 3;
    const int wm = (warp & 3) << 5;
    const int wn = (warp >> 2) << 6;

    // fused mask/stamp tail (gemm2 only)
    if (MODE == 1 && do_tail) {
        int gid = (bm * 8 + bn) * 256 + tid;
        if (gid < XROWS) {
            outp[XTOT + gid] = 1.0f;
            outp[XTOT + XROWS + gid] = (float)(gid % 1025);
        }
    }

    float acc[2][8][4];
    #pragma unroll
    for (int i = 0; i < 2; i++)
        #pragma unroll
        for (int j = 0; j < 8; j++)
            #pragma unroll
            for (int e = 0; e < 4; e++) acc[i][j][e] = 0.0f;

    issue_chunk<MODE>(smem, 0, 0, bm, bn, tid);
    asm volatile("cp.async.commit_group;" ::: "memory");
    issue_chunk<MODE>(smem, 1, 1, bm, bn, tid);
    asm volatile("cp.async.commit_group;" ::: "memory");

    int s = 0;
    for (int c = 0; c < NC; c++) {
        asm volatile("cp.async.wait_group 1;" ::: "memory");
        __syncthreads();
        if (c + 2 < NC) {
            int s2 = s + 2; if (s2 >= 3) s2 -= 3;
            issue_chunk<MODE>(smem, s2, c + 2, bm, bn, tid);
        }
        asm volatile("cp.async.commit_group;" ::: "memory");
        const unsigned* As = smem + s * STG_WORDS;
        compute_chunk(As, As + 4096, acc, wm, wn, g, t);
        if (++s == 3) s = 0;
    }

    // Epilogue. frag map: c0:(g,2t) c1:(g,2t+1) c2:(g+8,2t) c3:(g+8,2t+1)
    #pragma unroll
    for (int mi = 0; mi < 2; mi++) {
        const int m0 = bm * 128 + wm + (mi << 4) + g;
        const int m1 = m0 + 8;
        #pragma unroll
        for (int ni = 0; ni < 8; ni++) {
            const int n = bn * 128 + wn + (ni << 3) + (t << 1);
            const float2 bb = *(const float2*)(bias + n);
            if (MODE == 0) {
                {
                    const int b = m0 >> 10, p = m0 & 1023;
                    float2 v = make_float2(f2tff(gelu32(acc[mi][ni][0] + bb.x)),
                                           f2tff(gelu32(acc[mi][ni][1] + bb.y)));
                    *(float2*)&g_x1[((size_t)(b * 1025 + 1 + p) << 10) + n] = v;
                }
                {
                    const int b = m1 >> 10, p = m1 & 1023;
                    float2 v = make_float2(f2tff(gelu32(acc[mi][ni][2] + bb.x)),
                                           f2tff(gelu32(acc[mi][ni][3] + bb.y)));
                    *(float2*)&g_x1[((size_t)(b * 1025 + 1 + p) << 10) + n] = v;
                }
            } else {
                if (m0 < XROWS) {
                    const int p = m0 % 1025;
                    const float2 pv = *(const float2*)(pos + ((size_t)p << 10) + n);
                    float2 v = make_float2(acc[mi][ni][0] + bb.x + pv.x,
                                           acc[mi][ni][1] + bb.y + pv.y);
                    *(float2*)&outp[((size_t)m0 << 10) + n] = v;
                }
                if (m1 < XROWS) {
                    const int p = m1 % 1025;
                    const float2 pv = *(const float2*)(pos + ((size_t)p << 10) + n);
                    float2 v = make_float2(acc[mi][ni][2] + bb.x + pv.x,
                                           acc[mi][ni][3] + bb.y + pv.y);
                    *(float2*)&outp[((size_t)m1 << 10) + n] = v;
                }
            }
        }
    }
}

extern "C" void kernel_launch(void* const* d_in, const int* in_sizes, int n_in,
                              void* d_out, int out_size) {
    const float* spikes  = (const float*)d_in[0];
    const float* W_embed = (const float*)d_in[1];
    const float* b_embed = (const float*)d_in[2];
    const float* cls     = (const float*)d_in[3];
    const float* W_proj  = (const float*)d_in[4];
    const float* b_proj  = (const float*)d_in[5];
    const float* pos     = (const float*)d_in[6];
    float* outp = (float*)d_out;

    cudaFuncSetAttribute(fused_gemm<0>, cudaFuncAttributeMaxDynamicSharedMemorySize, SMEM_BYTES);
    cudaFuncSetAttribute(fused_gemm<1>, cudaFuncAttributeMaxDynamicSharedMemorySize, SMEM_BYTES);

    // 1) pre-convert to tf32 bits (+ cls rows of g_x1)
    convert_kernel<<<17952, 256>>>((const float4*)spikes, (const float4*)W_embed,
                                   (const float4*)W_proj, (const float4*)cls);

    // 2) patchify + embed + gelu*scale -> g_x1  (M=32768, K=512, N=1024)
    fused_gemm<0><<<dim3(8, 256), 256, SMEM_BYTES>>>(b_embed, nullptr, nullptr, 0);

    // 3) proj + bias + pos_table -> d_out (+mask/stamp)  (M=32800, K=1024, N=1024)
    int do_tail = ((long long)out_size >= XTOT + 2LL * XROWS) ? 1 : 0;
    fused_gemm<1><<<dim3(8, 257), 256, SMEM_BYTES>>>(b_proj, pos, outp, do_tail);
}